// round 7
// baseline (speedup 1.0000x reference)
#include <cuda_runtime.h>
#include <cstdint>

// LocalVariation: out[b, k, y, x] = x[b,0,y,x] - x_pad[b,0,y+i,x+j]
// 24 off-center (i,j) in 5x5 window, replicate padding.
// x [16,1,512,512] f32 -> out [16,24,512,512] f32.
//
// R7: persistent CTAs (760 = 5/SM x 152 SMs) + dynamic tile ticketing
// (global atomic, perfect balance) + cp.async double-buffered halo prefetch
// (overlaps next tile's input load with current tile's store stream).
// Compute core = R3: 128x16 tile, 2 rows/thread rolling window, float4 __stcs.

#define HH 512
#define WW 512
#define NB 16
#define NC 24
#define TX 128    // tile width (32 threads x float4)
#define TYO 16    // tile height (8 thread-rows x 2 rows)
#define SW 132    // TX + 4 halo
#define SH 20     // TYO + 4 halo
#define NTX 4
#define NTY 32
#define NT (NTX * NTY * NB)   // 2048 tiles
#define GRID 760              // 5 blocks/SM x 152 SMs

__device__ unsigned int g_ticket;

__global__ void zero_ticket_kernel() { g_ticket = 0; }

__device__ __forceinline__ void cp_async4(uint32_t dst_smem, const float* src) {
    asm volatile("cp.async.ca.shared.global [%0], [%1], 4;"
                 :: "r"(dst_smem), "l"(src));
}

__global__ __launch_bounds__(256, 5)
void local_variation_kernel(const float* __restrict__ x, float* __restrict__ out) {
    __shared__ float s[2][SH][SW];
    __shared__ unsigned int s_ticket;

    const int tid = threadIdx.y * 32 + threadIdx.x;

    // ---- halo prefetch for one tile into buffer `buf` (cp.async, clamped) ----
    auto issue_halo = [&](int tile, int buf) {
        int bx  = tile & (NTX - 1);
        int rem = tile >> 2;
        int by  = rem & (NTY - 1);
        int b   = rem >> 5;
        int x0 = bx * TX, y0 = by * TYO;
        const float* __restrict__ xb = x + (size_t)b * HH * WW;
        uint32_t sbase = (uint32_t)__cvta_generic_to_shared(&s[buf][0][0]);
        #pragma unroll 4
        for (int idx = tid; idx < SH * SW; idx += 256) {
            int r = idx / SW;
            int c = idx - r * SW;
            int gy = min(max(y0 + r - 2, 0), HH - 1);
            int gx = min(max(x0 + c - 2, 0), WW - 1);
            cp_async4(sbase + 4u * idx, xb + gy * WW + gx);
        }
        asm volatile("cp.async.commit_group;" ::: "memory");
    };

    // ---- compute + store one tile from buffer `buf` (R3 core) ----
    auto compute_tile = [&](int tile, int buf) {
        int bx  = tile & (NTX - 1);
        int rem = tile >> 2;
        int by  = rem & (NTY - 1);
        int b   = rem >> 5;
        int x0 = bx * TX, y0 = by * TYO;

        const int sx = threadIdx.x * 4;
        const int rb = threadIdx.y * 2;

        float w[5][8];
        #pragma unroll
        for (int i = 0; i < 5; i++) {
            float4 lo = *reinterpret_cast<const float4*>(&s[buf][rb + i][sx]);
            float4 hi = *reinterpret_cast<const float4*>(&s[buf][rb + i][sx + 4]);
            w[i][0] = lo.x; w[i][1] = lo.y; w[i][2] = lo.z; w[i][3] = lo.w;
            w[i][4] = hi.x; w[i][5] = hi.y; w[i][6] = hi.z; w[i][7] = hi.w;
        }

        const int gy0 = y0 + rb;
        const int gx  = x0 + sx;
        float* __restrict__ ob = out + (((size_t)b * NC) * HH + gy0) * WW + gx;
        const size_t plane = (size_t)HH * WW;

        #pragma unroll
        for (int t = 0; t < 2; t++) {
            const float* cw = w[(t + 2) % 5];
            const float c0 = cw[2], c1 = cw[3], c2 = cw[4], c3 = cw[5];
            float* __restrict__ orow = ob + t * WW;
            int k = 0;
            #pragma unroll
            for (int i = 0; i < 5; i++) {
                const float* rr = w[(t + i) % 5];
                #pragma unroll
                for (int j = 0; j < 5; j++) {
                    if (i == 2 && j == 2) continue;
                    float4 o;
                    o.x = c0 - rr[j + 0];
                    o.y = c1 - rr[j + 1];
                    o.z = c2 - rr[j + 2];
                    o.w = c3 - rr[j + 3];
                    __stcs(reinterpret_cast<float4*>(orow + (size_t)k * plane), o);
                    k++;
                }
            }
            if (t < 1) {
                float4 lo = *reinterpret_cast<const float4*>(&s[buf][rb + 5][sx]);
                float4 hi = *reinterpret_cast<const float4*>(&s[buf][rb + 5][sx + 4]);
                float* d = w[0];
                d[0] = lo.x; d[1] = lo.y; d[2] = lo.z; d[3] = lo.w;
                d[4] = hi.x; d[5] = hi.y; d[6] = hi.z; d[7] = hi.w;
            }
        }
    };

    // ---- prologue: grab first tile, start its halo load ----
    if (tid == 0) s_ticket = atomicAdd(&g_ticket, 1u);
    __syncthreads();
    int cur = (int)s_ticket;
    if (cur >= NT) return;              // uniform across block
    int cbuf = 0;
    issue_halo(cur, cbuf);

    // ---- pipelined tile loop ----
    while (true) {
        if (tid == 0) s_ticket = atomicAdd(&g_ticket, 1u);
        __syncthreads();                 // publish ticket; prev compute done with cbuf^1
        int next = (int)s_ticket;

        if (next < NT) {
            issue_halo(next, cbuf ^ 1);  // prefetch next tile while cur drains
            asm volatile("cp.async.wait_group 1;" ::: "memory");  // cur's group done
        } else {
            asm volatile("cp.async.wait_group 0;" ::: "memory");
        }
        __syncthreads();                 // cbuf contents visible to all threads

        compute_tile(cur, cbuf);

        if (next >= NT) break;
        cur = next;
        cbuf ^= 1;
    }
}

extern "C" void kernel_launch(void* const* d_in, const int* in_sizes, int n_in,
                              void* d_out, int out_size) {
    const float* x = (const float*)d_in[0];
    float* out = (float*)d_out;
    zero_ticket_kernel<<<1, 1>>>();
    dim3 block(32, 8, 1);
    local_variation_kernel<<<GRID, block>>>(x, out);
}

// round 9
// speedup vs baseline: 1.1203x; 1.1203x over previous
#include <cuda_runtime.h>

// LocalVariation: out[b, k, y, x] = x[b,0,y,x] - x_pad[b,0,y+i,x+j]
// 24 off-center (i,j) in 5x5 window, replicate padding.
// x [16,1,512,512] f32 -> out [16,24,512,512] f32.
//
// R9 = R3 core (128x16 tiles, 2048 blocks, rolling 2-row window, float4
// __stcs stores) + vectorized halo fill. Fix vs R8: interior smem columns
// 2+4*lane are only 8B-aligned, so the float4 gmem load is stored as TWO
// STS.64 (float2, 8B-aligned — legal) instead of one STS.128 (trapped).
// Halo phase: 1 LDG.128 + 2 STS.64 per thread-row (+4 edge scalars/warp)
// vs R3's 4 LDG.32 + 4 STS.32 -> ~60% fewer issues, ~3x fewer L1 wavefronts.

#define HH 512
#define WW 512
#define NB 16
#define NC 24
#define TX 128   // tile width (32 threads x float4)
#define TYO 16   // tile height (8 thread-rows x 2 rows)
#define SW 132   // TX + 4 halo
#define SH 20    // TYO + 4 halo

__global__ __launch_bounds__(256, 5)
void local_variation_kernel(const float* __restrict__ x, float* __restrict__ out) {
    __shared__ float s[SH][SW];

    const int warp = threadIdx.y;     // 0..7
    const int lane = threadIdx.x;     // 0..31
    const int x0 = blockIdx.x * TX;
    const int y0 = blockIdx.y * TYO;
    const int b  = blockIdx.z;

    const float* __restrict__ xb = x + (size_t)b * HH * WW;

    // ---- Vectorized halo fill: one warp per smem row ----
    // Interior halo cols c = 2+4*lane .. 5+4*lane <-> gx = x0+4*lane .. +3
    // (always in-image, gmem 16B-aligned). Smem col 2+4*lane is 8B-aligned,
    // so store the float4 as two float2 (STS.64).
    // Edges: lanes 0..3 cover halo cols 0,1,130,131 (x-clamped scalars).
    #pragma unroll
    for (int r = warp; r < SH; r += 8) {
        const int gy = min(max(y0 + r - 2, 0), HH - 1);
        const float* __restrict__ row = xb + gy * WW;

        float4 v = *reinterpret_cast<const float4*>(row + x0 + 4 * lane);
        *reinterpret_cast<float2*>(&s[r][2 + 4 * lane]) = make_float2(v.x, v.y);
        *reinterpret_cast<float2*>(&s[r][4 + 4 * lane]) = make_float2(v.z, v.w);

        if (lane < 4) {
            int c  = (lane < 2) ? lane : (128 + lane);   // 0,1,130,131
            int gx = min(max(x0 + c - 2, 0), WW - 1);
            s[r][c] = row[gx];
        }
    }
    __syncthreads();

    const int sx = lane * 4;          // tile-local col of first pixel
    const int rb = warp * 2;          // first output row (tile-local)

    // 5-row x 8-float rolling register window.
    // Invariant at step t: slot (t+i)%5 holds smem row rb+t+i.
    float w[5][8];
    #pragma unroll
    for (int i = 0; i < 5; i++) {
        float4 lo = *reinterpret_cast<const float4*>(&s[rb + i][sx]);
        float4 hi = *reinterpret_cast<const float4*>(&s[rb + i][sx + 4]);
        w[i][0] = lo.x; w[i][1] = lo.y; w[i][2] = lo.z; w[i][3] = lo.w;
        w[i][4] = hi.x; w[i][5] = hi.y; w[i][6] = hi.z; w[i][7] = hi.w;
    }

    const int gy0 = y0 + rb;
    const int gx  = x0 + sx;
    float* __restrict__ ob = out + (((size_t)b * NC) * HH + gy0) * WW + gx;
    const size_t plane = (size_t)HH * WW;

    #pragma unroll
    for (int t = 0; t < 2; t++) {
        const float* cw = w[(t + 2) % 5];
        const float c0 = cw[2], c1 = cw[3], c2 = cw[4], c3 = cw[5];

        float* __restrict__ orow = ob + t * WW;
        int k = 0;
        #pragma unroll
        for (int i = 0; i < 5; i++) {
            const float* rr = w[(t + i) % 5];
            #pragma unroll
            for (int j = 0; j < 5; j++) {
                if (i == 2 && j == 2) continue;
                float4 o;
                o.x = c0 - rr[j + 0];
                o.y = c1 - rr[j + 1];
                o.z = c2 - rr[j + 2];
                o.w = c3 - rr[j + 3];
                __stcs(reinterpret_cast<float4*>(orow + (size_t)k * plane), o);
                k++;
            }
        }

        // Roll: slot t%5 (held row rb+t) <- smem row rb+t+5.
        if (t < 1) {
            float4 lo = *reinterpret_cast<const float4*>(&s[rb + 5][sx]);
            float4 hi = *reinterpret_cast<const float4*>(&s[rb + 5][sx + 4]);
            float* d = w[0];
            d[0] = lo.x; d[1] = lo.y; d[2] = lo.z; d[3] = lo.w;
            d[4] = hi.x; d[5] = hi.y; d[6] = hi.z; d[7] = hi.w;
        }
    }
}

extern "C" void kernel_launch(void* const* d_in, const int* in_sizes, int n_in,
                              void* d_out, int out_size) {
    const float* x = (const float*)d_in[0];
    float* out = (float*)d_out;
    dim3 block(32, 8, 1);
    dim3 grid(WW / TX, HH / TYO, NB);   // 4 x 32 x 16 = 2048 blocks
    local_variation_kernel<<<grid, block>>>(x, out);
}